// round 1
// baseline (speedup 1.0000x reference)
#include <cuda_runtime.h>
#include <cuda_bf16.h>
#include <cstdint>

#define SEQ   4096
#define DIM   512
#define VOCAB 32000
#define NBLK  4

#define NCHUNK 32
#define CHUNK  (SEQ / NCHUNK)   // 128

// ---------------- scratch (no allocations allowed) ----------------
__device__ float g_x [SEQ * DIM];
__device__ float g_xn[SEQ * DIM];
__device__ float g_hg[SEQ * 2 * DIM];
__device__ float g_c [SEQ * DIM];
__device__ float g_w [SEQ * DIM];
__device__ float g_Cs   [NCHUNK * DIM];
__device__ float g_Ws   [NCHUNK * DIM];
__device__ float g_carry[NCHUNK * DIM];

// ---------------- elementwise kernels ----------------

__global__ void embed_kernel(const int* __restrict__ ids,
                             const float* __restrict__ emb,
                             float* __restrict__ x) {
    int idx = blockIdx.x * blockDim.x + threadIdx.x;     // over SEQ*DIM/4
    int t  = idx / (DIM / 4);
    int d4 = idx % (DIM / 4);
    const float4* src = (const float4*)(emb + (size_t)ids[t] * DIM);
    ((float4*)(x + (size_t)t * DIM))[d4] = src[d4];
}

__global__ void rmsnorm_kernel(const float* __restrict__ x,
                               const float* __restrict__ scale,
                               float* __restrict__ out) {
    int t = blockIdx.x;
    int tid = threadIdx.x;                                // 128 threads, 4 f32 each
    float4 v = ((const float4*)(x + (size_t)t * DIM))[tid];
    float ss = v.x * v.x + v.y * v.y + v.z * v.z + v.w * v.w;
    #pragma unroll
    for (int o = 16; o; o >>= 1) ss += __shfl_xor_sync(0xffffffffu, ss, o);
    __shared__ float sred[4];
    if ((tid & 31) == 0) sred[tid >> 5] = ss;
    __syncthreads();
    ss = sred[0] + sred[1] + sred[2] + sred[3];
    float r = rsqrtf(ss * (1.0f / DIM) + 1e-6f);
    float4 s = ((const float4*)scale)[tid];
    float4 o;
    o.x = v.x * r * s.x; o.y = v.y * r * s.y;
    o.z = v.z * r * s.z; o.w = v.w * r * s.w;
    ((float4*)(out + (size_t)t * DIM))[tid] = o;
}

// hg[t, 0:512] = hidden, hg[t, 512:1024] = gate
//   z = sigmoid(gate), c = sigmoid(-gate), g = (h>=0)? h+0.5 : sigmoid(h), w = z*g
__global__ void cw_kernel(const float* __restrict__ hg,
                          float* __restrict__ c,
                          float* __restrict__ w) {
    int idx = blockIdx.x * blockDim.x + threadIdx.x;     // SEQ*DIM
    int t = idx / DIM, d = idx % DIM;
    float hid = hg[(size_t)t * 2 * DIM + d];
    float gat = hg[(size_t)t * 2 * DIM + DIM + d];
    float z  = 1.0f / (1.0f + __expf(-gat));
    float cc = 1.0f / (1.0f + __expf(gat));              // exact sigmoid(-gate)
    float g  = (hid >= 0.0f) ? (hid + 0.5f) : (1.0f / (1.0f + __expf(-hid)));
    c[idx] = cc;
    w[idx] = z * g;
}

// ---------------- chunked linear scan:  h_t = c_t*h_{t-1} + w_t  ----------------

__global__ void scan_part1(const float* __restrict__ c, const float* __restrict__ w,
                           float* __restrict__ Cs, float* __restrict__ Ws) {
    int d = threadIdx.x;                                  // 512 threads = channels
    int b = blockIdx.x;                                   // 32 chunks
    float C = 1.0f, W = 0.0f;
    size_t base = (size_t)b * CHUNK * DIM + d;
    #pragma unroll 4
    for (int j = 0; j < CHUNK; j++) {
        float cc = c[base + (size_t)j * DIM];
        float ww = w[base + (size_t)j * DIM];
        W = fmaf(cc, W, ww);
        C *= cc;
    }
    Cs[b * DIM + d] = C;
    Ws[b * DIM + d] = W;
}

__global__ void scan_part2(const float* __restrict__ Cs, const float* __restrict__ Ws,
                           float* __restrict__ carry) {
    int d = threadIdx.x;
    float h = 0.0f;
    #pragma unroll
    for (int b = 0; b < NCHUNK; b++) {
        carry[b * DIM + d] = h;
        h = fmaf(Cs[b * DIM + d], h, Ws[b * DIM + d]);
    }
}

__global__ void scan_part3(const float* __restrict__ c, const float* __restrict__ w,
                           const float* __restrict__ carry, float* __restrict__ x) {
    int d = threadIdx.x;
    int b = blockIdx.x;
    float h = carry[b * DIM + d];
    size_t base = (size_t)b * CHUNK * DIM + d;
    #pragma unroll 4
    for (int j = 0; j < CHUNK; j++) {
        size_t p = base + (size_t)j * DIM;
        h = fmaf(c[p], h, w[p]);
        x[p] += h;                                        // residual add
    }
}

// ---------------- TF32 tensor-core GEMM:  C[M,N] = A[M,K] * B[K,N] ----------------
// A,B,C fp32 row-major; M,N,K multiples of 128/128/32 (always true here).

#define BM 128
#define BN 128
#define BK 32
#define ASTRIDE (BK + 4)   // 36, conflict-free for A frag loads, 16B-aligned rows
#define BSTRIDE (BN + 4)   // 132, conflict-free for B frag loads

__device__ __forceinline__ float cvt_tf32(float x) {
    uint32_t u;
    asm("cvt.rna.tf32.f32 %0, %1;" : "=r"(u) : "f"(x));
    return __uint_as_float(u);
}

__device__ __forceinline__ void mma_tf32(float* c, const uint32_t* a,
                                         uint32_t b0, uint32_t b1) {
    asm volatile(
        "mma.sync.aligned.m16n8k8.row.col.f32.tf32.tf32.f32 "
        "{%0,%1,%2,%3}, {%4,%5,%6,%7}, {%8,%9}, {%0,%1,%2,%3};"
        : "+f"(c[0]), "+f"(c[1]), "+f"(c[2]), "+f"(c[3])
        : "r"(a[0]), "r"(a[1]), "r"(a[2]), "r"(a[3]), "r"(b0), "r"(b1));
}

__global__ __launch_bounds__(256)
void gemm_tf32(const float* __restrict__ A, const float* __restrict__ B,
               float* __restrict__ C, int K, int N) {
    __shared__ float As[BM * ASTRIDE];
    __shared__ float Bs[BK * BSTRIDE];

    int tid  = threadIdx.x;
    int lane = tid & 31;
    int wid  = tid >> 5;
    int wm = wid & 3;          // warp row  (4 warps x 32 rows)
    int wn = wid >> 2;         // warp col  (2 warps x 64 cols)
    int bm = blockIdx.y, bn = blockIdx.x;

    const float* Ab = A + (size_t)bm * BM * K;
    const float* Bb = B + (size_t)bn * BN;

    float acc[2][8][4];
    #pragma unroll
    for (int mf = 0; mf < 2; mf++)
        #pragma unroll
        for (int nf = 0; nf < 8; nf++)
            #pragma unroll
            for (int i = 0; i < 4; i++) acc[mf][nf][i] = 0.0f;

    // gmem staging pattern
    int arow = tid >> 3;            // 0..31 (+i*32)
    int acol = (tid & 7) * 4;
    int brow = tid >> 5;            // 0..7  (+i*8)
    int bcol = (tid & 31) * 4;

    float4 ra[4], rb[4];
    #pragma unroll
    for (int i = 0; i < 4; i++)
        ra[i] = *(const float4*)(Ab + (size_t)(arow + i * 32) * K + acol);
    #pragma unroll
    for (int i = 0; i < 4; i++)
        rb[i] = *(const float4*)(Bb + (size_t)(brow + i * 8) * N + bcol);

    int NKT = K / BK;
    for (int kt = 0; kt < NKT; kt++) {
        // stage -> smem (pre-rounded to tf32)
        #pragma unroll
        for (int i = 0; i < 4; i++) {
            float4 v = ra[i];
            v.x = cvt_tf32(v.x); v.y = cvt_tf32(v.y);
            v.z = cvt_tf32(v.z); v.w = cvt_tf32(v.w);
            *(float4*)&As[(arow + i * 32) * ASTRIDE + acol] = v;
        }
        #pragma unroll
        for (int i = 0; i < 4; i++) {
            float4 v = rb[i];
            v.x = cvt_tf32(v.x); v.y = cvt_tf32(v.y);
            v.z = cvt_tf32(v.z); v.w = cvt_tf32(v.w);
            *(float4*)&Bs[(brow + i * 8) * BSTRIDE + bcol] = v;
        }
        __syncthreads();

        // prefetch next K-tile while computing this one
        if (kt + 1 < NKT) {
            const float* An = Ab + (kt + 1) * BK;
            #pragma unroll
            for (int i = 0; i < 4; i++)
                ra[i] = *(const float4*)(An + (size_t)(arow + i * 32) * K + acol);
            const float* Bn = Bb + (size_t)(kt + 1) * BK * N;
            #pragma unroll
            for (int i = 0; i < 4; i++)
                rb[i] = *(const float4*)(Bn + (size_t)(brow + i * 8) * N + bcol);
        }

        #pragma unroll
        for (int ks = 0; ks < 4; ks++) {
            int k0 = ks * 8;
            int kc = k0 + (lane & 3);
            uint32_t af[2][4];
            int r0 = wm * 32 + (lane >> 2);
            #pragma unroll
            for (int mf = 0; mf < 2; mf++) {
                int r = r0 + mf * 16;
                af[mf][0] = __float_as_uint(As[r        * ASTRIDE + kc]);
                af[mf][1] = __float_as_uint(As[(r + 8)  * ASTRIDE + kc]);
                af[mf][2] = __float_as_uint(As[r        * ASTRIDE + kc + 4]);
                af[mf][3] = __float_as_uint(As[(r + 8)  * ASTRIDE + kc + 4]);
            }
            #pragma unroll
            for (int nf = 0; nf < 8; nf++) {
                int col = wn * 64 + nf * 8 + (lane >> 2);
                uint32_t b0 = __float_as_uint(Bs[kc       * BSTRIDE + col]);
                uint32_t b1 = __float_as_uint(Bs[(kc + 4) * BSTRIDE + col]);
                #pragma unroll
                for (int mf = 0; mf < 2; mf++)
                    mma_tf32(acc[mf][nf], af[mf], b0, b1);
            }
        }
        __syncthreads();
    }

    // epilogue
    #pragma unroll
    for (int mf = 0; mf < 2; mf++) {
        int r = bm * BM + wm * 32 + mf * 16 + (lane >> 2);
        #pragma unroll
        for (int nf = 0; nf < 8; nf++) {
            int cc = bn * BN + wn * 64 + nf * 8 + (lane & 3) * 2;
            *(float2*)&C[(size_t)r       * N + cc] = make_float2(acc[mf][nf][0], acc[mf][nf][1]);
            *(float2*)&C[(size_t)(r + 8) * N + cc] = make_float2(acc[mf][nf][2], acc[mf][nf][3]);
        }
    }
}

// ---------------- host launch ----------------

extern "C" void kernel_launch(void* const* d_in, const int* in_sizes, int n_in,
                              void* d_out, int out_size) {
    const int*   ids         = (const int*)  d_in[0];
    const float* emb         = (const float*)d_in[1];
    const float* w_hg        = (const float*)d_in[2];
    const float* norm_scales = (const float*)d_in[3];
    const float* final_scale = (const float*)d_in[4];
    const float* readout     = (const float*)d_in[5];
    float* out = (float*)d_out;

    float *x, *xn, *hg, *c, *w, *Cs, *Ws, *carry;
    cudaGetSymbolAddress((void**)&x,     g_x);
    cudaGetSymbolAddress((void**)&xn,    g_xn);
    cudaGetSymbolAddress((void**)&hg,    g_hg);
    cudaGetSymbolAddress((void**)&c,     g_c);
    cudaGetSymbolAddress((void**)&w,     g_w);
    cudaGetSymbolAddress((void**)&Cs,    g_Cs);
    cudaGetSymbolAddress((void**)&Ws,    g_Ws);
    cudaGetSymbolAddress((void**)&carry, g_carry);

    embed_kernel<<<(SEQ * DIM / 4) / 256, 256>>>(ids, emb, x);

    for (int i = 0; i < NBLK; i++) {
        rmsnorm_kernel<<<SEQ, 128>>>(x, norm_scales + i * DIM, xn);
        gemm_tf32<<<dim3(2 * DIM / BN, SEQ / BM), 256>>>(
            xn, w_hg + (size_t)i * DIM * 2 * DIM, hg, DIM, 2 * DIM);
        cw_kernel<<<(SEQ * DIM) / 256, 256>>>(hg, c, w);
        scan_part1<<<NCHUNK, DIM>>>(c, w, Cs, Ws);
        scan_part2<<<1, DIM>>>(Cs, Ws, carry);
        scan_part3<<<NCHUNK, DIM>>>(c, w, carry, x);
    }

    rmsnorm_kernel<<<SEQ, 128>>>(x, final_scale, xn);
    gemm_tf32<<<dim3(VOCAB / BN, SEQ / BM), 256>>>(xn, readout, out, DIM, VOCAB);

    (void)in_sizes; (void)n_in; (void)out_size;
}

// round 2
// speedup vs baseline: 1.1455x; 1.1455x over previous
#include <cuda_runtime.h>
#include <cuda_bf16.h>
#include <cstdint>

#define SEQ   4096
#define DIM   512
#define VOCAB 32000
#define NBLK  4

#define NCHUNK 128
#define CHUNK  (SEQ / NCHUNK)   // 32

// ---------------- scratch (no allocations allowed) ----------------
__device__ float g_x [SEQ * DIM];
__device__ float g_xn[SEQ * DIM];
__device__ float g_hg[SEQ * 2 * DIM];
__device__ float g_c [SEQ * DIM];
__device__ float g_w [SEQ * DIM];
__device__ float g_Cs   [NCHUNK * DIM];
__device__ float g_Ws   [NCHUNK * DIM];
__device__ float g_carry[NCHUNK * DIM];
__device__ float g_ro_r [DIM * VOCAB];        // tf32-rounded readout weight
__device__ float g_whg_r[NBLK * DIM * 2 * DIM]; // tf32-rounded block weights

__device__ __forceinline__ float cvt_tf32(float x) {
    uint32_t u;
    asm("cvt.rna.tf32.f32 %0, %1;" : "=r"(u) : "f"(x));
    return __uint_as_float(u);
}

// ---------------- elementwise kernels ----------------

__global__ void embed_kernel(const int* __restrict__ ids,
                             const float* __restrict__ emb,
                             float* __restrict__ x) {
    int idx = blockIdx.x * blockDim.x + threadIdx.x;     // over SEQ*DIM/4
    int t  = idx / (DIM / 4);
    int d4 = idx % (DIM / 4);
    const float4* src = (const float4*)(emb + (size_t)ids[t] * DIM);
    ((float4*)(x + (size_t)t * DIM))[d4] = src[d4];
}

// rounds a float buffer to tf32 (rna), vectorized
__global__ void round_tf32_kernel(const float* __restrict__ s, float* __restrict__ d) {
    int i = blockIdx.x * blockDim.x + threadIdx.x;
    float4 v = ((const float4*)s)[i];
    v.x = cvt_tf32(v.x); v.y = cvt_tf32(v.y);
    v.z = cvt_tf32(v.z); v.w = cvt_tf32(v.w);
    ((float4*)d)[i] = v;
}

// rmsnorm; output pre-rounded to tf32 (it only feeds GEMM A operands)
__global__ void rmsnorm_kernel(const float* __restrict__ x,
                               const float* __restrict__ scale,
                               float* __restrict__ out) {
    int t = blockIdx.x;
    int tid = threadIdx.x;                                // 128 threads, 4 f32 each
    float4 v = ((const float4*)(x + (size_t)t * DIM))[tid];
    float ss = v.x * v.x + v.y * v.y + v.z * v.z + v.w * v.w;
    #pragma unroll
    for (int o = 16; o; o >>= 1) ss += __shfl_xor_sync(0xffffffffu, ss, o);
    __shared__ float sred[4];
    if ((tid & 31) == 0) sred[tid >> 5] = ss;
    __syncthreads();
    ss = sred[0] + sred[1] + sred[2] + sred[3];
    float r = rsqrtf(ss * (1.0f / DIM) + 1e-6f);
    float4 s = ((const float4*)scale)[tid];
    float4 o;
    o.x = cvt_tf32(v.x * r * s.x); o.y = cvt_tf32(v.y * r * s.y);
    o.z = cvt_tf32(v.z * r * s.z); o.w = cvt_tf32(v.w * r * s.w);
    ((float4*)(out + (size_t)t * DIM))[tid] = o;
}

// ---------------- fused cw + chunk summaries ----------------
// c = sigmoid(-gate), w = sigmoid(gate)*g(hidden); per-chunk (prod c, scan w)
__global__ void cwscan1_kernel(const float* __restrict__ hg,
                               float* __restrict__ c, float* __restrict__ w,
                               float* __restrict__ Cs, float* __restrict__ Ws) {
    int d = threadIdx.x;                                  // 512 channels
    int b = blockIdx.x;                                   // NCHUNK chunks
    float C = 1.0f, W = 0.0f;
    #pragma unroll 4
    for (int j = 0; j < CHUNK; j++) {
        int t = b * CHUNK + j;
        float hid = hg[(size_t)t * 2 * DIM + d];
        float gat = hg[(size_t)t * 2 * DIM + DIM + d];
        float z  = 1.0f / (1.0f + __expf(-gat));
        float cc = 1.0f / (1.0f + __expf(gat));
        float g  = (hid >= 0.0f) ? (hid + 0.5f) : (1.0f / (1.0f + __expf(-hid)));
        float ww = z * g;
        c[(size_t)t * DIM + d] = cc;
        w[(size_t)t * DIM + d] = ww;
        W = fmaf(cc, W, ww);
        C *= cc;
    }
    Cs[b * DIM + d] = C;
    Ws[b * DIM + d] = W;
}

__global__ void scan_part2(const float* __restrict__ Cs, const float* __restrict__ Ws,
                           float* __restrict__ carry) {
    int d = threadIdx.x;
    float h = 0.0f;
    #pragma unroll 8
    for (int b = 0; b < NCHUNK; b++) {
        carry[b * DIM + d] = h;
        h = fmaf(Cs[b * DIM + d], h, Ws[b * DIM + d]);
    }
}

__global__ void scan_part3(const float* __restrict__ c, const float* __restrict__ w,
                           const float* __restrict__ carry, float* __restrict__ x) {
    int d = threadIdx.x;
    int b = blockIdx.x;
    float h = carry[b * DIM + d];
    size_t base = (size_t)b * CHUNK * DIM + d;
    #pragma unroll 4
    for (int j = 0; j < CHUNK; j++) {
        size_t p = base + (size_t)j * DIM;
        h = fmaf(c[p], h, w[p]);
        x[p] += h;                                        // residual add
    }
}

// ---------------- pipelined TF32 tensor-core GEMM ----------------
// C[M,N] = A[M,K]*B[K,N], fp32 row-major, operands pre-rounded to tf32.
// BM=256, BN=128, BK=32, 256 threads, 3-stage cp.async pipeline.

#define BM 256
#define BN 128
#define BK 32
#define ASTR 36         // A smem row stride (floats): conflict-free, 16B-aligned rows
#define BSTR 136        // B smem row stride: conflict-free frag loads, 16B-aligned
#define ASZ (BM * ASTR) // 9216 floats
#define BSZ (BK * BSTR) // 4352 floats
#define STAGE_SZ (ASZ + BSZ)
#define STAGES 3
#define GEMM_SMEM_BYTES (STAGES * STAGE_SZ * 4)   // 162816

__device__ __forceinline__ void cp_async16(float* smem, const float* gmem) {
    uint32_t s = (uint32_t)__cvta_generic_to_shared(smem);
    asm volatile("cp.async.cg.shared.global [%0], [%1], 16;\n" :: "r"(s), "l"(gmem));
}
#define CP_COMMIT() asm volatile("cp.async.commit_group;\n" ::: "memory")
#define CP_WAIT1()  asm volatile("cp.async.wait_group 1;\n" ::: "memory")

__device__ __forceinline__ void mma_tf32(float* c, const uint32_t* a,
                                         uint32_t b0, uint32_t b1) {
    asm volatile(
        "mma.sync.aligned.m16n8k8.row.col.f32.tf32.tf32.f32 "
        "{%0,%1,%2,%3}, {%4,%5,%6,%7}, {%8,%9}, {%0,%1,%2,%3};"
        : "+f"(c[0]), "+f"(c[1]), "+f"(c[2]), "+f"(c[3])
        : "r"(a[0]), "r"(a[1]), "r"(a[2]), "r"(a[3]), "r"(b0), "r"(b1));
}

__device__ __forceinline__ void load_stage(float* sA, float* sB,
                                           const float* Ab, const float* Bb,
                                           int kt, int K, int N, int tid) {
    const float* Ag = Ab + kt * BK;
    int arow = tid >> 3;
    int acol = (tid & 7) * 4;
    #pragma unroll
    for (int i = 0; i < 8; i++)
        cp_async16(&sA[(arow + i * 32) * ASTR + acol],
                   Ag + (size_t)(arow + i * 32) * K + acol);
    const float* Bg = Bb + (size_t)kt * BK * N;
    int brow = tid >> 3;
    int bcol = (tid & 7) * 4;
    #pragma unroll
    for (int j = 0; j < 4; j++)
        cp_async16(&sB[brow * BSTR + bcol + j * 32],
                   Bg + (size_t)brow * N + bcol + j * 32);
}

__global__ __launch_bounds__(256)
void gemm_pipe(const float* __restrict__ A, const float* __restrict__ B,
               float* __restrict__ C, int K, int N) {
    extern __shared__ float sm[];
    int tid  = threadIdx.x;
    int lane = tid & 31;
    int wid  = tid >> 5;
    int wm = wid & 3;                 // 4 m-warps (64 rows each)
    int wn = wid >> 2;                // 2 n-warps (64 cols each)
    int bm = blockIdx.x, bn = blockIdx.y;   // m-fastest wave order (L2 reuse of B stripe)

    const float* Ab = A + (size_t)bm * BM * K;
    const float* Bb = B + (size_t)bn * BN;

    float acc[4][8][4];
    #pragma unroll
    for (int mf = 0; mf < 4; mf++)
        #pragma unroll
        for (int nf = 0; nf < 8; nf++)
            #pragma unroll
            for (int i = 0; i < 4; i++) acc[mf][nf][i] = 0.0f;

    int NKT = K / BK;

    #pragma unroll
    for (int s = 0; s < STAGES - 1; s++) {
        load_stage(sm + s * STAGE_SZ, sm + s * STAGE_SZ + ASZ, Ab, Bb, s, K, N, tid);
        CP_COMMIT();
    }

    for (int kt = 0; kt < NKT; kt++) {
        CP_WAIT1();
        __syncthreads();

        int nk = kt + STAGES - 1;
        if (nk < NKT) {
            int st = nk % STAGES;
            load_stage(sm + st * STAGE_SZ, sm + st * STAGE_SZ + ASZ, Ab, Bb, nk, K, N, tid);
        }
        CP_COMMIT();

        const float* As_ = sm + (kt % STAGES) * STAGE_SZ;
        const float* Bs_ = As_ + ASZ;

        #pragma unroll
        for (int ks = 0; ks < 4; ks++) {
            int kc = ks * 8 + (lane & 3);
            uint32_t af[4][4];
            #pragma unroll
            for (int mf = 0; mf < 4; mf++) {
                int r = wm * 64 + mf * 16 + (lane >> 2);
                af[mf][0] = __float_as_uint(As_[r       * ASTR + kc]);
                af[mf][1] = __float_as_uint(As_[(r + 8) * ASTR + kc]);
                af[mf][2] = __float_as_uint(As_[r       * ASTR + kc + 4]);
                af[mf][3] = __float_as_uint(As_[(r + 8) * ASTR + kc + 4]);
            }
            #pragma unroll
            for (int nf = 0; nf < 8; nf++) {
                int col = wn * 64 + nf * 8 + (lane >> 2);
                uint32_t b0 = __float_as_uint(Bs_[kc       * BSTR + col]);
                uint32_t b1 = __float_as_uint(Bs_[(kc + 4) * BSTR + col]);
                #pragma unroll
                for (int mf = 0; mf < 4; mf++)
                    mma_tf32(acc[mf][nf], af[mf], b0, b1);
            }
        }
        // no trailing barrier needed: the barrier after CP_WAIT1 next iteration
        // orders this compute before any overwrite of its stage.
    }

    #pragma unroll
    for (int mf = 0; mf < 4; mf++) {
        int r = bm * BM + wm * 64 + mf * 16 + (lane >> 2);
        #pragma unroll
        for (int nf = 0; nf < 8; nf++) {
            int cc = bn * BN + wn * 64 + nf * 8 + (lane & 3) * 2;
            *(float2*)&C[(size_t)r       * N + cc] = make_float2(acc[mf][nf][0], acc[mf][nf][1]);
            *(float2*)&C[(size_t)(r + 8) * N + cc] = make_float2(acc[mf][nf][2], acc[mf][nf][3]);
        }
    }
}

// ---------------- host launch ----------------

extern "C" void kernel_launch(void* const* d_in, const int* in_sizes, int n_in,
                              void* d_out, int out_size) {
    const int*   ids         = (const int*)  d_in[0];
    const float* emb         = (const float*)d_in[1];
    const float* w_hg        = (const float*)d_in[2];
    const float* norm_scales = (const float*)d_in[3];
    const float* final_scale = (const float*)d_in[4];
    const float* readout     = (const float*)d_in[5];
    float* out = (float*)d_out;

    float *x, *xn, *hg, *c, *w, *Cs, *Ws, *carry, *ro_r, *whg_r;
    cudaGetSymbolAddress((void**)&x,     g_x);
    cudaGetSymbolAddress((void**)&xn,    g_xn);
    cudaGetSymbolAddress((void**)&hg,    g_hg);
    cudaGetSymbolAddress((void**)&c,     g_c);
    cudaGetSymbolAddress((void**)&w,     g_w);
    cudaGetSymbolAddress((void**)&Cs,    g_Cs);
    cudaGetSymbolAddress((void**)&Ws,    g_Ws);
    cudaGetSymbolAddress((void**)&carry, g_carry);
    cudaGetSymbolAddress((void**)&ro_r,  g_ro_r);
    cudaGetSymbolAddress((void**)&whg_r, g_whg_r);

    static int smem_set = 0;
    if (!smem_set) {
        cudaFuncSetAttribute(gemm_pipe, cudaFuncAttributeMaxDynamicSharedMemorySize,
                             GEMM_SMEM_BYTES);
        smem_set = 1;
    }

    // pre-round weights to tf32 (once per replay; ~20us of HBM traffic)
    round_tf32_kernel<<<(DIM * VOCAB / 4) / 256, 256>>>(readout, ro_r);
    round_tf32_kernel<<<(NBLK * DIM * 2 * DIM / 4) / 256, 256>>>(w_hg, whg_r);

    embed_kernel<<<(SEQ * DIM / 4) / 256, 256>>>(ids, emb, x);

    for (int i = 0; i < NBLK; i++) {
        rmsnorm_kernel<<<SEQ, 128>>>(x, norm_scales + i * DIM, xn);
        gemm_pipe<<<dim3(SEQ / BM, 2 * DIM / BN), 256, GEMM_SMEM_BYTES>>>(
            xn, whg_r + (size_t)i * DIM * 2 * DIM, hg, DIM, 2 * DIM);
        cwscan1_kernel<<<NCHUNK, DIM>>>(hg, c, w, Cs, Ws);
        scan_part2<<<1, DIM>>>(Cs, Ws, carry);
        scan_part3<<<NCHUNK, DIM>>>(c, w, carry, x);
    }

    rmsnorm_kernel<<<SEQ, 128>>>(x, final_scale, xn);
    gemm_pipe<<<dim3(SEQ / BM, VOCAB / BN), 256, GEMM_SMEM_BYTES>>>(
        xn, ro_r, out, DIM, VOCAB);

    (void)in_sizes; (void)n_in; (void)out_size;
}

// round 4
// speedup vs baseline: 1.3123x; 1.1456x over previous
#include <cuda_runtime.h>
#include <cuda_bf16.h>
#include <cstdint>

#define SEQ   4096
#define DIM   512
#define VOCAB 32000
#define NBLK  4

#define NCHUNK 128
#define CHUNK  (SEQ / NCHUNK)   // 32

// ---------------- scratch (no allocations allowed) ----------------
__device__ float g_x [SEQ * DIM];
__device__ float g_xn[SEQ * DIM];
__device__ float g_hg[SEQ * 2 * DIM];
__device__ float g_c [SEQ * DIM];
__device__ float g_w [SEQ * DIM];
__device__ float g_Cs   [NCHUNK * DIM];
__device__ float g_Ws   [NCHUNK * DIM];
__device__ float g_carry[NCHUNK * DIM];
__device__ float g_roT [VOCAB * DIM];             // readout^T  [32000, 512], tf32-rounded
__device__ float g_whgT[NBLK * 2 * DIM * DIM];    // w_hg^T per block [1024, 512], tf32-rounded

// ---------------- helpers ----------------
__device__ __forceinline__ float cvt_tf32(float x) {
    uint32_t u;
    asm("cvt.rna.tf32.f32 %0, %1;" : "=r"(u) : "f"(x));
    return __uint_as_float(u);
}
__device__ __forceinline__ uint32_t smem_u32(const void* p) {
    return (uint32_t)__cvta_generic_to_shared(p);
}
__device__ __forceinline__ void cp_async16(uint32_t saddr, const float* gmem) {
    asm volatile("cp.async.cg.shared.global [%0], [%1], 16;\n" :: "r"(saddr), "l"(gmem));
}
#define CP_COMMIT() asm volatile("cp.async.commit_group;\n" ::: "memory")
#define CP_WAIT2()  asm volatile("cp.async.wait_group 2;\n" ::: "memory")

#define LDSM4(r, addr) \
    asm volatile("ldmatrix.sync.aligned.m8n8.x4.shared.b16 {%0,%1,%2,%3}, [%4];" \
        : "=r"((r)[0]), "=r"((r)[1]), "=r"((r)[2]), "=r"((r)[3]) : "r"(addr))

__device__ __forceinline__ void mma_tf32(float* c, const uint32_t* a,
                                         uint32_t b0, uint32_t b1) {
    asm volatile(
        "mma.sync.aligned.m16n8k8.row.col.f32.tf32.tf32.f32 "
        "{%0,%1,%2,%3}, {%4,%5,%6,%7}, {%8,%9}, {%0,%1,%2,%3};"
        : "+f"(c[0]), "+f"(c[1]), "+f"(c[2]), "+f"(c[3])
        : "r"(a[0]), "r"(a[1]), "r"(a[2]), "r"(a[3]), "r"(b0), "r"(b1));
}

// ---------------- elementwise kernels ----------------

__global__ void embed_kernel(const int* __restrict__ ids,
                             const float* __restrict__ emb,
                             float* __restrict__ x) {
    int idx = blockIdx.x * blockDim.x + threadIdx.x;
    int t  = idx / (DIM / 4);
    int d4 = idx % (DIM / 4);
    const float4* src = (const float4*)(emb + (size_t)ids[t] * DIM);
    ((float4*)(x + (size_t)t * DIM))[d4] = src[d4];
}

// src [K, N] row-major  ->  dst [N, K] row-major, rounded to tf32 (rna)
__global__ void transpose_round(const float* __restrict__ src0, float* __restrict__ dst0,
                                int K, int N) {
    const float* src = src0 + (size_t)blockIdx.z * K * N;
    float* dst = dst0 + (size_t)blockIdx.z * N * K;
    __shared__ float t[32][33];
    int n0 = blockIdx.x * 32, k0 = blockIdx.y * 32;
    int tx = threadIdx.x, ty = threadIdx.y;                 // 32 x 8
    #pragma unroll
    for (int i = 0; i < 32; i += 8)
        t[ty + i][tx] = src[(size_t)(k0 + ty + i) * N + n0 + tx];
    __syncthreads();
    #pragma unroll
    for (int i = 0; i < 32; i += 8)
        dst[(size_t)(n0 + ty + i) * K + k0 + tx] = cvt_tf32(t[tx][ty + i]);
}

// rmsnorm; output pre-rounded to tf32 (feeds GEMM A operands only)
__global__ void rmsnorm_kernel(const float* __restrict__ x,
                               const float* __restrict__ scale,
                               float* __restrict__ out) {
    int t = blockIdx.x;
    int tid = threadIdx.x;                                // 128 threads, 4 f32 each
    float4 v = ((const float4*)(x + (size_t)t * DIM))[tid];
    float ss = v.x * v.x + v.y * v.y + v.z * v.z + v.w * v.w;
    #pragma unroll
    for (int o = 16; o; o >>= 1) ss += __shfl_xor_sync(0xffffffffu, ss, o);
    __shared__ float sred[4];
    if ((tid & 31) == 0) sred[tid >> 5] = ss;
    __syncthreads();
    ss = sred[0] + sred[1] + sred[2] + sred[3];
    float r = rsqrtf(ss * (1.0f / DIM) + 1e-6f);
    float4 s = ((const float4*)scale)[tid];
    float4 o;
    o.x = cvt_tf32(v.x * r * s.x); o.y = cvt_tf32(v.y * r * s.y);
    o.z = cvt_tf32(v.z * r * s.z); o.w = cvt_tf32(v.w * r * s.w);
    ((float4*)(out + (size_t)t * DIM))[tid] = o;
}

// ---------------- fused cw + chunk summaries ----------------
__global__ void cwscan1_kernel(const float* __restrict__ hg,
                               float* __restrict__ c, float* __restrict__ w,
                               float* __restrict__ Cs, float* __restrict__ Ws) {
    int d = threadIdx.x;
    int b = blockIdx.x;
    float C = 1.0f, W = 0.0f;
    #pragma unroll 4
    for (int j = 0; j < CHUNK; j++) {
        int t = b * CHUNK + j;
        float hid = hg[(size_t)t * 2 * DIM + d];
        float gat = hg[(size_t)t * 2 * DIM + DIM + d];
        float z  = 1.0f / (1.0f + __expf(-gat));
        float cc = 1.0f / (1.0f + __expf(gat));
        float g  = (hid >= 0.0f) ? (hid + 0.5f) : (1.0f / (1.0f + __expf(-hid)));
        float ww = z * g;
        c[(size_t)t * DIM + d] = cc;
        w[(size_t)t * DIM + d] = ww;
        W = fmaf(cc, W, ww);
        C *= cc;
    }
    Cs[b * DIM + d] = C;
    Ws[b * DIM + d] = W;
}

__global__ void scan_part2(const float* __restrict__ Cs, const float* __restrict__ Ws,
                           float* __restrict__ carry) {
    int d = threadIdx.x;
    float h = 0.0f;
    #pragma unroll 8
    for (int b = 0; b < NCHUNK; b++) {
        carry[b * DIM + d] = h;
        h = fmaf(Cs[b * DIM + d], h, Ws[b * DIM + d]);
    }
}

__global__ void scan_part3(const float* __restrict__ c, const float* __restrict__ w,
                           const float* __restrict__ carry, float* __restrict__ x) {
    int d = threadIdx.x;
    int b = blockIdx.x;
    float h = carry[b * DIM + d];
    size_t base = (size_t)b * CHUNK * DIM + d;
    #pragma unroll 4
    for (int j = 0; j < CHUNK; j++) {
        size_t p = base + (size_t)j * DIM;
        h = fmaf(c[p], h, w[p]);
        x[p] += h;
    }
}

// ---------------- tf32 mma.sync GEMM with ldmatrix fragments ----------------
// C[M, N] = A[M, 512] * BT[N, 512]^T.  A, BT fp32 pre-rounded to tf32.
// CTA 128x256, warp tile 64x64 (2x4 warps), BK=32, 4-stage cp.async pipeline.
// Smem layout: 128-byte rows (32 floats), 16B chunk j swizzled by ^(row&7).

#define GK  512
#define NKT 16
#define BM  128
#define BN  256
#define GSTAGES 4
#define A_BYTES (BM * 128)                 // 16 KB
#define B_BYTES (BN * 128)                 // 32 KB
#define STAGE_BYTES (A_BYTES + B_BYTES)    // 48 KB
#define GEMM_SMEM (GSTAGES * STAGE_BYTES)  // 192 KB

__device__ __forceinline__ void load_stage_g(uint32_t sbase, int stage,
                                             const float* Ab, const float* Bb,
                                             int kt, int tid) {
    uint32_t sa = sbase + stage * STAGE_BYTES;
    int j = tid & 7;                       // 16B chunk within 128B row
    int rt = tid >> 3;                     // 0..31
    const float* Ag = Ab + kt * 32 + j * 4;
    #pragma unroll
    for (int i = 0; i < 4; i++) {
        int r = i * 32 + rt;
        cp_async16(sa + r * 128 + ((j ^ (r & 7)) << 4), Ag + (size_t)r * GK);
    }
    uint32_t sb = sa + A_BYTES;
    const float* Bg = Bb + kt * 32 + j * 4;
    #pragma unroll
    for (int i = 0; i < 8; i++) {
        int r = i * 32 + rt;
        cp_async16(sb + r * 128 + ((j ^ (r & 7)) << 4), Bg + (size_t)r * GK);
    }
}

__global__ __launch_bounds__(256)
void gemm_mma(const float* __restrict__ A, const float* __restrict__ BT,
              float* __restrict__ C, int N) {
    extern __shared__ char smc[];
    uint32_t sbase = smem_u32(smc);

    int tid  = threadIdx.x;
    int lane = tid & 31;
    int wid  = tid >> 5;
    int wm = wid & 1;                 // 2 m-warps (64 rows each)
    int wn = wid >> 1;                // 4 n-warps (64 cols each)
    int bm = blockIdx.x, bn = blockIdx.y;

    const float* Ab = A  + (size_t)bm * BM * GK;
    const float* Bb = BT + (size_t)bn * BN * GK;

    float acc[4][8][4];
    #pragma unroll
    for (int mf = 0; mf < 4; mf++)
        #pragma unroll
        for (int nf = 0; nf < 8; nf++)
            #pragma unroll
            for (int i = 0; i < 4; i++) acc[mf][nf][i] = 0.0f;

    // per-thread ldmatrix address components
    int arow_l = (lane & 7) + ((lane >> 3) & 1) * 8;   // A: row within 16-row group
    int adj    = (lane >> 4) & 1;                      // A: k-chunk select
    int brow_l = (lane & 7) + ((lane >> 4) & 1) * 8;   // B: row within 16-row group
    int bdj    = (lane >> 3) & 1;                      // B: k-chunk select

    #pragma unroll
    for (int s = 0; s < GSTAGES - 1; s++) {
        load_stage_g(sbase, s, Ab, Bb, s, tid);
        CP_COMMIT();
    }

    for (int kt = 0; kt < NKT; kt++) {
        CP_WAIT2();
        __syncthreads();

        if (kt + GSTAGES - 1 < NKT)
            load_stage_g(sbase, (kt + GSTAGES - 1) % GSTAGES, Ab, Bb,
                         kt + GSTAGES - 1, tid);
        CP_COMMIT();

        uint32_t sa = sbase + (kt % GSTAGES) * STAGE_BYTES;
        uint32_t sb = sa + A_BYTES;

        #pragma unroll
        for (int ks = 0; ks < 4; ks++) {
            uint32_t a[4][4];
            #pragma unroll
            for (int mf = 0; mf < 4; mf++) {
                int row = wm * 64 + mf * 16 + arow_l;
                int jj  = (ks * 2 + adj) ^ (row & 7);
                LDSM4(a[mf], sa + row * 128 + (jj << 4));
            }
            #pragma unroll
            for (int nfp = 0; nfp < 4; nfp++) {
                int row = wn * 64 + nfp * 16 + brow_l;
                int jj  = (ks * 2 + bdj) ^ (row & 7);
                uint32_t b[4];
                LDSM4(b, sb + row * 128 + (jj << 4));
                #pragma unroll
                for (int mf = 0; mf < 4; mf++)
                    mma_tf32(acc[mf][2 * nfp], a[mf], b[0], b[1]);
                #pragma unroll
                for (int mf = 0; mf < 4; mf++)
                    mma_tf32(acc[mf][2 * nfp + 1], a[mf], b[2], b[3]);
            }
        }
    }

    // epilogue: c0,c1 at (row, col..col+1), c2,c3 at (row+8, ...)
    #pragma unroll
    for (int mf = 0; mf < 4; mf++) {
        int r = bm * BM + wm * 64 + mf * 16 + (lane >> 2);
        #pragma unroll
        for (int nf = 0; nf < 8; nf++) {
            int cc = bn * BN + wn * 64 + nf * 8 + (lane & 3) * 2;
            *(float2*)&C[(size_t)r       * N + cc] = make_float2(acc[mf][nf][0], acc[mf][nf][1]);
            *(float2*)&C[(size_t)(r + 8) * N + cc] = make_float2(acc[mf][nf][2], acc[mf][nf][3]);
        }
    }
}

// ---------------- host launch ----------------

extern "C" void kernel_launch(void* const* d_in, const int* in_sizes, int n_in,
                              void* d_out, int out_size) {
    const int*   ids         = (const int*)  d_in[0];
    const float* emb         = (const float*)d_in[1];
    const float* w_hg        = (const float*)d_in[2];
    const float* norm_scales = (const float*)d_in[3];
    const float* final_scale = (const float*)d_in[4];
    const float* readout     = (const float*)d_in[5];
    float* out = (float*)d_out;

    float *x, *xn, *hg, *c, *w, *Cs, *Ws, *carry, *roT, *whgT;
    cudaGetSymbolAddress((void**)&x,     g_x);
    cudaGetSymbolAddress((void**)&xn,    g_xn);
    cudaGetSymbolAddress((void**)&hg,    g_hg);
    cudaGetSymbolAddress((void**)&c,     g_c);
    cudaGetSymbolAddress((void**)&w,     g_w);
    cudaGetSymbolAddress((void**)&Cs,    g_Cs);
    cudaGetSymbolAddress((void**)&Ws,    g_Ws);
    cudaGetSymbolAddress((void**)&carry, g_carry);
    cudaGetSymbolAddress((void**)&roT,   g_roT);
    cudaGetSymbolAddress((void**)&whgT,  g_whgT);

    cudaFuncSetAttribute(gemm_mma, cudaFuncAttributeMaxDynamicSharedMemorySize, GEMM_SMEM);

    // transpose + tf32-round weights (once per replay)
    transpose_round<<<dim3(VOCAB / 32, DIM / 32, 1), dim3(32, 8)>>>(readout, roT, DIM, VOCAB);
    transpose_round<<<dim3(2 * DIM / 32, DIM / 32, NBLK), dim3(32, 8)>>>(w_hg, whgT, DIM, 2 * DIM);

    embed_kernel<<<(SEQ * DIM / 4) / 256, 256>>>(ids, emb, x);

    for (int i = 0; i < NBLK; i++) {
        rmsnorm_kernel<<<SEQ, 128>>>(x, norm_scales + i * DIM, xn);
        gemm_mma<<<dim3(SEQ / BM, 2 * DIM / BN), 256, GEMM_SMEM>>>(
            xn, whgT + (size_t)i * 2 * DIM * DIM, hg, 2 * DIM);
        cwscan1_kernel<<<NCHUNK, DIM>>>(hg, c, w, Cs, Ws);
        scan_part2<<<1, DIM>>>(Cs, Ws, carry);
        scan_part3<<<NCHUNK, DIM>>>(c, w, carry, x);
    }

    rmsnorm_kernel<<<SEQ, 128>>>(x, final_scale, xn);
    gemm_mma<<<dim3(SEQ / BM, VOCAB / BN), 256, GEMM_SMEM>>>(xn, roT, out, VOCAB);

    (void)in_sizes; (void)n_in; (void)out_size;
}

// round 5
// speedup vs baseline: 2.0492x; 1.5616x over previous
#include <cuda_runtime.h>
#include <cuda_fp16.h>
#include <cstdint>

#define SEQ   4096
#define DIM   512
#define VOCAB 32000
#define NBLK  4

#define NCHUNK 128
#define CHUNK  (SEQ / NCHUNK)   // 32

// ---------------- scratch (no allocations allowed) ----------------
__device__ float  g_x [SEQ * DIM];
__device__ __half g_xn[SEQ * DIM];                  // fp16 rmsnorm output (GEMM A)
__device__ float  g_hg[SEQ * 2 * DIM];
__device__ float  g_c [SEQ * DIM];
__device__ float  g_w [SEQ * DIM];
__device__ float  g_Cs   [NCHUNK * DIM];
__device__ float  g_Ws   [NCHUNK * DIM];
__device__ float  g_carry[NCHUNK * DIM];
__device__ __half g_roT [VOCAB * DIM];              // readout^T  [32000, 512] fp16
__device__ __half g_whgT[NBLK * 2 * DIM * DIM];     // w_hg^T per block [1024, 512] fp16

// ---------------- helpers ----------------
__device__ __forceinline__ uint32_t smem_u32(const void* p) {
    return (uint32_t)__cvta_generic_to_shared(p);
}
__device__ __forceinline__ void cp_async16(uint32_t saddr, const void* gmem) {
    asm volatile("cp.async.cg.shared.global [%0], [%1], 16;\n" :: "r"(saddr), "l"(gmem));
}
#define CP_COMMIT() asm volatile("cp.async.commit_group;\n" ::: "memory")
#define CP_WAIT2()  asm volatile("cp.async.wait_group 2;\n" ::: "memory")

#define LDSM4(r, addr) \
    asm volatile("ldmatrix.sync.aligned.m8n8.x4.shared.b16 {%0,%1,%2,%3}, [%4];" \
        : "=r"((r)[0]), "=r"((r)[1]), "=r"((r)[2]), "=r"((r)[3]) : "r"(addr))

__device__ __forceinline__ void mma_f16(float* c, const uint32_t* a,
                                        uint32_t b0, uint32_t b1) {
    asm volatile(
        "mma.sync.aligned.m16n8k16.row.col.f32.f16.f16.f32 "
        "{%0,%1,%2,%3}, {%4,%5,%6,%7}, {%8,%9}, {%0,%1,%2,%3};"
        : "+f"(c[0]), "+f"(c[1]), "+f"(c[2]), "+f"(c[3])
        : "r"(a[0]), "r"(a[1]), "r"(a[2]), "r"(a[3]), "r"(b0), "r"(b1));
}

// ---------------- elementwise kernels ----------------

__global__ void embed_kernel(const int* __restrict__ ids,
                             const float* __restrict__ emb,
                             float* __restrict__ x) {
    int idx = blockIdx.x * blockDim.x + threadIdx.x;
    int t  = idx / (DIM / 4);
    int d4 = idx % (DIM / 4);
    const float4* src = (const float4*)(emb + (size_t)ids[t] * DIM);
    ((float4*)(x + (size_t)t * DIM))[d4] = src[d4];
}

// src [K, N] row-major f32  ->  dst [N, K] row-major fp16
__global__ void transpose_h(const float* __restrict__ src0, __half* __restrict__ dst0,
                            int K, int N) {
    const float* src = src0 + (size_t)blockIdx.z * K * N;
    __half* dst = dst0 + (size_t)blockIdx.z * N * K;
    __shared__ float t[32][33];
    int n0 = blockIdx.x * 32, k0 = blockIdx.y * 32;
    int tx = threadIdx.x, ty = threadIdx.y;                 // 32 x 8
    #pragma unroll
    for (int i = 0; i < 32; i += 8)
        t[ty + i][tx] = src[(size_t)(k0 + ty + i) * N + n0 + tx];
    __syncthreads();
    #pragma unroll
    for (int i = 0; i < 32; i += 8)
        dst[(size_t)(n0 + ty + i) * K + k0 + tx] = __float2half_rn(t[tx][ty + i]);
}

// rmsnorm; output fp16 (feeds GEMM A operands only; residual stream stays f32)
__global__ void rmsnorm_kernel(const float* __restrict__ x,
                               const float* __restrict__ scale,
                               __half* __restrict__ out) {
    int t = blockIdx.x;
    int tid = threadIdx.x;                                // 128 threads, 4 f32 each
    float4 v = ((const float4*)(x + (size_t)t * DIM))[tid];
    float ss = v.x * v.x + v.y * v.y + v.z * v.z + v.w * v.w;
    #pragma unroll
    for (int o = 16; o; o >>= 1) ss += __shfl_xor_sync(0xffffffffu, ss, o);
    __shared__ float sred[4];
    if ((tid & 31) == 0) sred[tid >> 5] = ss;
    __syncthreads();
    ss = sred[0] + sred[1] + sred[2] + sred[3];
    float r = rsqrtf(ss * (1.0f / DIM) + 1e-6f);
    float4 s = ((const float4*)scale)[tid];
    __half2 h0 = __floats2half2_rn(v.x * r * s.x, v.y * r * s.y);
    __half2 h1 = __floats2half2_rn(v.z * r * s.z, v.w * r * s.w);
    ((__half2*)(out + (size_t)t * DIM))[2 * tid]     = h0;
    ((__half2*)(out + (size_t)t * DIM))[2 * tid + 1] = h1;
}

// ---------------- fused cw + chunk summaries ----------------
__global__ void cwscan1_kernel(const float* __restrict__ hg,
                               float* __restrict__ c, float* __restrict__ w,
                               float* __restrict__ Cs, float* __restrict__ Ws) {
    int d = threadIdx.x;
    int b = blockIdx.x;
    float C = 1.0f, W = 0.0f;
    #pragma unroll 4
    for (int j = 0; j < CHUNK; j++) {
        int t = b * CHUNK + j;
        float hid = hg[(size_t)t * 2 * DIM + d];
        float gat = hg[(size_t)t * 2 * DIM + DIM + d];
        float z  = 1.0f / (1.0f + __expf(-gat));
        float cc = 1.0f / (1.0f + __expf(gat));
        float g  = (hid >= 0.0f) ? (hid + 0.5f) : (1.0f / (1.0f + __expf(-hid)));
        float ww = z * g;
        c[(size_t)t * DIM + d] = cc;
        w[(size_t)t * DIM + d] = ww;
        W = fmaf(cc, W, ww);
        C *= cc;
    }
    Cs[b * DIM + d] = C;
    Ws[b * DIM + d] = W;
}

__global__ void scan_part2(const float* __restrict__ Cs, const float* __restrict__ Ws,
                           float* __restrict__ carry) {
    int d = threadIdx.x;
    float h = 0.0f;
    #pragma unroll 8
    for (int b = 0; b < NCHUNK; b++) {
        carry[b * DIM + d] = h;
        h = fmaf(Cs[b * DIM + d], h, Ws[b * DIM + d]);
    }
}

__global__ void scan_part3(const float* __restrict__ c, const float* __restrict__ w,
                           const float* __restrict__ carry, float* __restrict__ x) {
    int d = threadIdx.x;
    int b = blockIdx.x;
    float h = carry[b * DIM + d];
    size_t base = (size_t)b * CHUNK * DIM + d;
    #pragma unroll 4
    for (int j = 0; j < CHUNK; j++) {
        size_t p = base + (size_t)j * DIM;
        h = fmaf(c[p], h, w[p]);
        x[p] += h;
    }
}

// ---------------- fp16 mma.sync GEMM (m16n8k16) ----------------
// C[M, N] = A[M, 512] * BT[N, 512]^T.  A, BT fp16, C f32.
// CTA 128x256, warp tile 64x64 (2x4 warps), BK=64, 4-stage cp.async pipeline.
// Smem: 128-byte rows (64 halves), 16B chunk j swizzled by ^(row&7).

#define GK  512
#define GBK 64
#define NKT (GK / GBK)                     // 8
#define BM  128
#define BN  256
#define GSTAGES 4
#define A_BYTES (BM * 128)                 // 16 KB
#define B_BYTES (BN * 128)                 // 32 KB
#define STAGE_BYTES (A_BYTES + B_BYTES)    // 48 KB
#define GEMM_SMEM (GSTAGES * STAGE_BYTES)  // 192 KB

__device__ __forceinline__ void load_stage_g(uint32_t sbase, int stage,
                                             const __half* Ab, const __half* Bb,
                                             int kt, int tid) {
    uint32_t sa = sbase + stage * STAGE_BYTES;
    int j = tid & 7;                       // 16B chunk within 128B row (8 halves)
    int rt = tid >> 3;                     // 0..31
    const __half* Ag = Ab + kt * GBK + j * 8;
    #pragma unroll
    for (int i = 0; i < 4; i++) {
        int r = i * 32 + rt;
        cp_async16(sa + r * 128 + ((j ^ (r & 7)) << 4), Ag + (size_t)r * GK);
    }
    uint32_t sb = sa + A_BYTES;
    const __half* Bg = Bb + kt * GBK + j * 8;
    #pragma unroll
    for (int i = 0; i < 8; i++) {
        int r = i * 32 + rt;
        cp_async16(sb + r * 128 + ((j ^ (r & 7)) << 4), Bg + (size_t)r * GK);
    }
}

__global__ __launch_bounds__(256)
void gemm_mma(const __half* __restrict__ A, const __half* __restrict__ BT,
              float* __restrict__ C, int N) {
    extern __shared__ char smc[];
    uint32_t sbase = smem_u32(smc);

    int tid  = threadIdx.x;
    int lane = tid & 31;
    int wid  = tid >> 5;
    int wm = wid & 1;                 // 2 m-warps (64 rows each)
    int wn = wid >> 1;                // 4 n-warps (64 cols each)
    int bm = blockIdx.x, bn = blockIdx.y;

    const __half* Ab = A  + (size_t)bm * BM * GK;
    const __half* Bb = BT + (size_t)bn * BN * GK;

    float acc[4][8][4];
    #pragma unroll
    for (int mf = 0; mf < 4; mf++)
        #pragma unroll
        for (int nf = 0; nf < 8; nf++)
            #pragma unroll
            for (int i = 0; i < 4; i++) acc[mf][nf][i] = 0.0f;

    // per-thread ldmatrix address components (b16 x4 quadrant mapping)
    int arow_l = (lane & 7) + ((lane >> 3) & 1) * 8;   // A: row within 16-row group
    int adj    = (lane >> 4) & 1;                      // A: k-chunk select (k8 step)
    int brow_l = (lane & 7) + ((lane >> 4) & 1) * 8;   // B: row within 16-row group
    int bdj    = (lane >> 3) & 1;                      // B: k-chunk select

    #pragma unroll
    for (int s = 0; s < GSTAGES - 1; s++) {
        load_stage_g(sbase, s, Ab, Bb, s, tid);
        CP_COMMIT();
    }

    for (int kt = 0; kt < NKT; kt++) {
        CP_WAIT2();
        __syncthreads();

        if (kt + GSTAGES - 1 < NKT)
            load_stage_g(sbase, (kt + GSTAGES - 1) % GSTAGES, Ab, Bb,
                         kt + GSTAGES - 1, tid);
        CP_COMMIT();

        uint32_t sa = sbase + (kt % GSTAGES) * STAGE_BYTES;
        uint32_t sb = sa + A_BYTES;

        #pragma unroll
        for (int ks = 0; ks < 4; ks++) {        // 4 x k16 per 64-wide tile
            uint32_t a[4][4];
            #pragma unroll
            for (int mf = 0; mf < 4; mf++) {
                int row = wm * 64 + mf * 16 + arow_l;
                int jj  = (ks * 2 + adj) ^ (row & 7);
                LDSM4(a[mf], sa + row * 128 + (jj << 4));
            }
            #pragma unroll
            for (int nfp = 0; nfp < 4; nfp++) {
                int row = wn * 64 + nfp * 16 + brow_l;
                int jj  = (ks * 2 + bdj) ^ (row & 7);
                uint32_t b[4];
                LDSM4(b, sb + row * 128 + (jj << 4));
                #pragma unroll
                for (int mf = 0; mf < 4; mf++)
                    mma_f16(acc[mf][2 * nfp], a[mf], b[0], b[1]);
                #pragma unroll
                for (int mf = 0; mf < 4; mf++)
                    mma_f16(acc[mf][2 * nfp + 1], a[mf], b[2], b[3]);
            }
        }
    }

    // epilogue: c0,c1 at (row, col..col+1), c2,c3 at (row+8, ...)
    #pragma unroll
    for (int mf = 0; mf < 4; mf++) {
        int r = bm * BM + wm * 64 + mf * 16 + (lane >> 2);
        #pragma unroll
        for (int nf = 0; nf < 8; nf++) {
            int cc = bn * BN + wn * 64 + nf * 8 + (lane & 3) * 2;
            *(float2*)&C[(size_t)r       * N + cc] = make_float2(acc[mf][nf][0], acc[mf][nf][1]);
            *(float2*)&C[(size_t)(r + 8) * N + cc] = make_float2(acc[mf][nf][2], acc[mf][nf][3]);
        }
    }
}

// ---------------- host launch ----------------

extern "C" void kernel_launch(void* const* d_in, const int* in_sizes, int n_in,
                              void* d_out, int out_size) {
    const int*   ids         = (const int*)  d_in[0];
    const float* emb         = (const float*)d_in[1];
    const float* w_hg        = (const float*)d_in[2];
    const float* norm_scales = (const float*)d_in[3];
    const float* final_scale = (const float*)d_in[4];
    const float* readout     = (const float*)d_in[5];
    float* out = (float*)d_out;

    float *x, *hg, *c, *w, *Cs, *Ws, *carry;
    __half *xn, *roT, *whgT;
    cudaGetSymbolAddress((void**)&x,     g_x);
    cudaGetSymbolAddress((void**)&xn,    g_xn);
    cudaGetSymbolAddress((void**)&hg,    g_hg);
    cudaGetSymbolAddress((void**)&c,     g_c);
    cudaGetSymbolAddress((void**)&w,     g_w);
    cudaGetSymbolAddress((void**)&Cs,    g_Cs);
    cudaGetSymbolAddress((void**)&Ws,    g_Ws);
    cudaGetSymbolAddress((void**)&carry, g_carry);
    cudaGetSymbolAddress((void**)&roT,   g_roT);
    cudaGetSymbolAddress((void**)&whgT,  g_whgT);

    cudaFuncSetAttribute(gemm_mma, cudaFuncAttributeMaxDynamicSharedMemorySize, GEMM_SMEM);

    // transpose + fp16-convert weights (once per replay)
    transpose_h<<<dim3(VOCAB / 32, DIM / 32, 1), dim3(32, 8)>>>(readout, roT, DIM, VOCAB);
    transpose_h<<<dim3(2 * DIM / 32, DIM / 32, NBLK), dim3(32, 8)>>>(w_hg, whgT, DIM, 2 * DIM);

    embed_kernel<<<(SEQ * DIM / 4) / 256, 256>>>(ids, emb, x);

    for (int i = 0; i < NBLK; i++) {
        rmsnorm_kernel<<<SEQ, 128>>>(x, norm_scales + i * DIM, xn);
        gemm_mma<<<dim3(SEQ / BM, 2 * DIM / BN), 256, GEMM_SMEM>>>(
            xn, whgT + (size_t)i * 2 * DIM * DIM, hg, 2 * DIM);
        cwscan1_kernel<<<NCHUNK, DIM>>>(hg, c, w, Cs, Ws);
        scan_part2<<<1, DIM>>>(Cs, Ws, carry);
        scan_part3<<<NCHUNK, DIM>>>(c, w, carry, x);
    }

    rmsnorm_kernel<<<SEQ, 128>>>(x, final_scale, xn);
    gemm_mma<<<dim3(SEQ / BM, VOCAB / BN), 256, GEMM_SMEM>>>(xn, roT, out, VOCAB);

    (void)in_sizes; (void)n_in; (void)out_size;
}